// round 2
// baseline (speedup 1.0000x reference)
#include <cuda_runtime.h>
#include <cstdint>

#define B_    16
#define H_    8
#define N_    1024
#define DIM_  512
#define KD_   32
#define D_    128
#define BH_   (B_*H_)

// ---- scratch (device globals; no allocations allowed) ----
__device__ float g_q[(size_t)BH_ * KD_ * N_];   // 16 MB, q pre-scaled by 1/sqrt(32)
__device__ float g_k[(size_t)BH_ * KD_ * N_];   // 16 MB
__device__ float g_v[(size_t)BH_ * D_  * N_];   // 64 MB
__device__ float g_p[(size_t)BH_ * N_  * N_];   // 512 MB softmax probs
__device__ float g_o[(size_t)B_ * (H_*D_) * N_]; // 64 MB relu(attention out)

// FMA-only exp (avoids MUFU.EX2 throughput wall: 134M exps needed)
__device__ __forceinline__ float fexp(float x) {
    float t = x * 1.4426950408889634f;      // x * log2(e)
    t = fmaxf(t, -126.0f);
    float fi = rintf(t);
    float f  = t - fi;
    // 2^f, f in [-0.5, 0.5], Taylor deg-5 (rel err ~2e-6)
    float p = 1.3333558146428443e-3f;
    p = fmaf(p, f, 9.618129107628477e-3f);
    p = fmaf(p, f, 5.550410866482158e-2f);
    p = fmaf(p, f, 2.402265069591007e-1f);
    p = fmaf(p, f, 6.931471805599453e-1f);
    p = fmaf(p, f, 1.0f);
    float s = __int_as_float(((int)fi + 127) << 23);
    return p * s;
}

// ======================================================================
// Kernel 1: grouped 1x1 conv (QKV). Per (b,h): C[192 x 1024] = W[192x64] @ X[64x1024] + b
// 64x64 block tile, BK=16, 4x4 per thread. Scatter rows to g_q (scaled) / g_k / g_v.
// ======================================================================
__global__ __launch_bounds__(256) void k_qkv(const float* __restrict__ x,
                                             const float* __restrict__ w,
                                             const float* __restrict__ bias) {
    __shared__ float As[16 * 64];
    __shared__ float Bs[16 * 64];
    int bh = blockIdx.z;
    int b = bh >> 3, h = bh & 7;
    int o0 = blockIdx.y * 64;
    int n0 = blockIdx.x * 64;
    int tid = threadIdx.x;

    const float* A  = w + (size_t)h * 192 * 64;
    const float* Bx = x + ((size_t)b * DIM_ + h * 64) * N_;

    int ai = tid >> 2, ak4 = (tid & 3) * 4;   // A: 64 rows x 16 k
    int bk = tid >> 4, bj4 = (tid & 15) * 4;  // B: 16 k x 64 j
    int ty = tid >> 4, tx = tid & 15;

    float acc[4][4] = {};
    for (int k0 = 0; k0 < 64; k0 += 16) {
        float4 av = *(const float4*)&A[(size_t)(o0 + ai) * 64 + k0 + ak4];
        float4 bv = *(const float4*)&Bx[(size_t)(k0 + bk) * N_ + n0 + bj4];
        __syncthreads();
        As[(ak4 + 0) * 64 + ai] = av.x;
        As[(ak4 + 1) * 64 + ai] = av.y;
        As[(ak4 + 2) * 64 + ai] = av.z;
        As[(ak4 + 3) * 64 + ai] = av.w;
        *(float4*)&Bs[bk * 64 + bj4] = bv;
        __syncthreads();
#pragma unroll
        for (int kk = 0; kk < 16; kk++) {
            float4 a4 = *(float4*)&As[kk * 64 + ty * 4];
            float4 b4 = *(float4*)&Bs[kk * 64 + tx * 4];
            float ar[4] = {a4.x, a4.y, a4.z, a4.w};
            float br[4] = {b4.x, b4.y, b4.z, b4.w};
#pragma unroll
            for (int i = 0; i < 4; i++)
#pragma unroll
                for (int j = 0; j < 4; j++)
                    acc[i][j] = fmaf(ar[i], br[j], acc[i][j]);
        }
    }

    const float SCALE = 0.17677669529663687f;  // 1/sqrt(32)
#pragma unroll
    for (int r = 0; r < 4; r++) {
        int oo = o0 + ty * 4 + r;
        float bb = bias[h * 192 + oo];
        float4 v;
        v.x = acc[r][0] + bb; v.y = acc[r][1] + bb;
        v.z = acc[r][2] + bb; v.w = acc[r][3] + bb;
        size_t n = (size_t)(n0 + tx * 4);
        if (oo < 32) {
            v.x *= SCALE; v.y *= SCALE; v.z *= SCALE; v.w *= SCALE;
            *(float4*)&g_q[((size_t)bh * KD_ + oo) * N_ + n] = v;
        } else if (oo < 64) {
            *(float4*)&g_k[((size_t)bh * KD_ + (oo - 32)) * N_ + n] = v;
        } else {
            *(float4*)&g_v[((size_t)bh * D_ + (oo - 64)) * N_ + n] = v;
        }
    }
}

// ======================================================================
// Kernel 2: scores + softmax. Per (b,h, 32 rows m): s[r][n] = q[:,m].k[:,n],
// full 32x1024 score tile in smem, warp-per-row softmax with FMA exp, write p.
// Dynamic smem: 32*1024 + 32*32 + 32*128 floats = 148 KB.
// ======================================================================
#define K2_SMEM_FLOATS (32 * 1024 + 32 * 32 + 32 * 128)
#define K2_SMEM_BYTES  (K2_SMEM_FLOATS * 4)

__global__ __launch_bounds__(256) void k_scores() {
    extern __shared__ float sm[];
    float* sc = sm;                 // [32][1024]
    float* qs = sm + 32 * 1024;     // [32 c][32 r]
    float* ks = qs + 32 * 32;       // [32 c][128 n]

    int bh = blockIdx.y;
    int m0 = blockIdx.x * 32;
    int tid = threadIdx.x;
    const float* Q = g_q + (size_t)bh * KD_ * N_;
    const float* K = g_k + (size_t)bh * KD_ * N_;

    {   // q tile: 32c x 32r
        int c = tid >> 3, r4 = (tid & 7) * 4;
        *(float4*)&qs[c * 32 + r4] = *(const float4*)&Q[(size_t)c * N_ + m0 + r4];
    }
    int ty = tid >> 5, tx = tid & 31;   // 8 row-groups x 32 n-groups

    for (int nc = 0; nc < 8; nc++) {
        int n0 = nc * 128;
        __syncthreads();
#pragma unroll
        for (int i = 0; i < 4; i++) {
            int idx = tid + i * 256;
            int c = idx >> 5, n4 = (idx & 31) * 4;
            *(float4*)&ks[c * 128 + n4] = *(const float4*)&K[(size_t)c * N_ + n0 + n4];
        }
        __syncthreads();
        float acc[4][4] = {};
#pragma unroll
        for (int c = 0; c < 32; c++) {
            float4 q4 = *(float4*)&qs[c * 32 + ty * 4];
            float4 k4 = *(float4*)&ks[c * 128 + tx * 4];
            float qr[4] = {q4.x, q4.y, q4.z, q4.w};
            float kr[4] = {k4.x, k4.y, k4.z, k4.w};
#pragma unroll
            for (int i = 0; i < 4; i++)
#pragma unroll
                for (int j = 0; j < 4; j++)
                    acc[i][j] = fmaf(qr[i], kr[j], acc[i][j]);
        }
#pragma unroll
        for (int r = 0; r < 4; r++) {
            float4 v; v.x = acc[r][0]; v.y = acc[r][1]; v.z = acc[r][2]; v.w = acc[r][3];
            *(float4*)&sc[(ty * 4 + r) * 1024 + n0 + tx * 4] = v;
        }
    }
    __syncthreads();

    // softmax: one warp per row (4 rows per warp), contiguous float4 lanes
    int w = tid >> 5, lane = tid & 31;
    float* pbase = g_p + ((size_t)bh * N_ + m0) * N_;
#pragma unroll
    for (int rr = 0; rr < 4; rr++) {
        int r = w * 4 + rr;
        const float* row = sc + r * 1024;
        float4 ev[8];
        float mx = -1e30f;
#pragma unroll
        for (int it = 0; it < 8; it++) {
            ev[it] = *(const float4*)&row[it * 128 + lane * 4];
            mx = fmaxf(mx, fmaxf(fmaxf(ev[it].x, ev[it].y), fmaxf(ev[it].z, ev[it].w)));
        }
#pragma unroll
        for (int o = 16; o; o >>= 1) mx = fmaxf(mx, __shfl_xor_sync(0xffffffffu, mx, o));
        float sum = 0.f;
#pragma unroll
        for (int it = 0; it < 8; it++) {
            ev[it].x = fexp(ev[it].x - mx);
            ev[it].y = fexp(ev[it].y - mx);
            ev[it].z = fexp(ev[it].z - mx);
            ev[it].w = fexp(ev[it].w - mx);
            sum += (ev[it].x + ev[it].y) + (ev[it].z + ev[it].w);
        }
#pragma unroll
        for (int o = 16; o; o >>= 1) sum += __shfl_xor_sync(0xffffffffu, sum, o);
        float rinv = 1.0f / sum;
        float* pr = pbase + (size_t)r * N_;
#pragma unroll
        for (int it = 0; it < 8; it++) {
            float4 v = ev[it];
            v.x *= rinv; v.y *= rinv; v.z *= rinv; v.w *= rinv;
            *(float4*)&pr[it * 128 + lane * 4] = v;
        }
    }
}

// ======================================================================
// Kernel 3: O = V @ P^T per (b,h): C[128 d][1024 m], K = 1024 n. ReLU fused.
// 128x128 tile, BK=8, 8x8 per thread.
// ======================================================================
__global__ __launch_bounds__(256) void k_av() {
    __shared__ float As[8 * 128];
    __shared__ float Bs[8 * 128];
    int bh = blockIdx.y;
    int m0 = blockIdx.x * 128;
    int b = bh >> 3, h = bh & 7;
    int tid = threadIdx.x;

    const float* V = g_v + (size_t)bh * D_ * N_;
    const float* P = g_p + (size_t)bh * N_ * N_;

    int ai = tid >> 1, a4 = (tid & 1) * 4;   // A: 128 rows x 8 k (contig along k)
    int bj = tid >> 1, b4 = (tid & 1) * 4;   // B[k][j] = P[m0+j][k] (contig along k)
    int ty = tid >> 4, tx = tid & 15;

    float acc[8][8] = {};
    for (int k0 = 0; k0 < N_; k0 += 8) {
        float4 av = *(const float4*)&V[(size_t)ai * N_ + k0 + a4];
        float4 bv = *(const float4*)&P[(size_t)(m0 + bj) * N_ + k0 + b4];
        __syncthreads();
        As[(a4 + 0) * 128 + ai] = av.x;
        As[(a4 + 1) * 128 + ai] = av.y;
        As[(a4 + 2) * 128 + ai] = av.z;
        As[(a4 + 3) * 128 + ai] = av.w;
        Bs[(b4 + 0) * 128 + bj] = bv.x;
        Bs[(b4 + 1) * 128 + bj] = bv.y;
        Bs[(b4 + 2) * 128 + bj] = bv.z;
        Bs[(b4 + 3) * 128 + bj] = bv.w;
        __syncthreads();
#pragma unroll
        for (int kk = 0; kk < 8; kk++) {
            float4 a0 = *(float4*)&As[kk * 128 + ty * 8];
            float4 a1 = *(float4*)&As[kk * 128 + ty * 8 + 4];
            float4 b0 = *(float4*)&Bs[kk * 128 + tx * 8];
            float4 b1 = *(float4*)&Bs[kk * 128 + tx * 8 + 4];
            float ar[8] = {a0.x, a0.y, a0.z, a0.w, a1.x, a1.y, a1.z, a1.w};
            float br[8] = {b0.x, b0.y, b0.z, b0.w, b1.x, b1.y, b1.z, b1.w};
#pragma unroll
            for (int i = 0; i < 8; i++)
#pragma unroll
                for (int j = 0; j < 8; j++)
                    acc[i][j] = fmaf(ar[i], br[j], acc[i][j]);
        }
    }

    float* O = g_o + ((size_t)b * (H_ * D_) + h * D_) * N_ + m0;
#pragma unroll
    for (int r = 0; r < 8; r++) {
        int d = ty * 8 + r;
        float4 v0, v1;
        v0.x = fmaxf(acc[r][0], 0.f); v0.y = fmaxf(acc[r][1], 0.f);
        v0.z = fmaxf(acc[r][2], 0.f); v0.w = fmaxf(acc[r][3], 0.f);
        v1.x = fmaxf(acc[r][4], 0.f); v1.y = fmaxf(acc[r][5], 0.f);
        v1.z = fmaxf(acc[r][6], 0.f); v1.w = fmaxf(acc[r][7], 0.f);
        *(float4*)&O[(size_t)d * N_ + tx * 8]     = v0;
        *(float4*)&O[(size_t)d * N_ + tx * 8 + 4] = v1;
    }
}

// ======================================================================
// Kernel 4: out = BN(proj_w @ o + proj_b). Per b: C[512 oc][1024 n], K = 1024 c.
// 128x128 tile, BK=8, 8x8 per thread.
// ======================================================================
__global__ __launch_bounds__(256) void k_proj(const float* __restrict__ pw,
                                              const float* __restrict__ pb,
                                              const float* __restrict__ gamma,
                                              const float* __restrict__ beta,
                                              const float* __restrict__ mean,
                                              const float* __restrict__ var,
                                              float* __restrict__ out) {
    __shared__ float As[8 * 128];
    __shared__ float Bs[8 * 128];
    int b   = blockIdx.z;
    int oc0 = blockIdx.y * 128;
    int n0  = blockIdx.x * 128;
    int tid = threadIdx.x;

    const float* A  = pw;                              // [512 x 1024]
    const float* Bm = g_o + (size_t)b * 1024 * N_;     // [1024 x 1024]

    int ai = tid >> 1, a4 = (tid & 1) * 4;     // A: 128 rows x 8 k
    int bk = tid >> 5, bj4 = (tid & 31) * 4;   // B: 8 k x 128 j (contig along j)
    int ty = tid >> 4, tx = tid & 15;

    float acc[8][8] = {};
    for (int k0 = 0; k0 < 1024; k0 += 8) {
        float4 av = *(const float4*)&A[(size_t)(oc0 + ai) * 1024 + k0 + a4];
        float4 bv = *(const float4*)&Bm[(size_t)(k0 + bk) * N_ + n0 + bj4];
        __syncthreads();
        As[(a4 + 0) * 128 + ai] = av.x;
        As[(a4 + 1) * 128 + ai] = av.y;
        As[(a4 + 2) * 128 + ai] = av.z;
        As[(a4 + 3) * 128 + ai] = av.w;
        *(float4*)&Bs[bk * 128 + bj4] = bv;
        __syncthreads();
#pragma unroll
        for (int kk = 0; kk < 8; kk++) {
            float4 a0 = *(float4*)&As[kk * 128 + ty * 8];
            float4 a1 = *(float4*)&As[kk * 128 + ty * 8 + 4];
            float4 b0 = *(float4*)&Bs[kk * 128 + tx * 8];
            float4 b1 = *(float4*)&Bs[kk * 128 + tx * 8 + 4];
            float ar[8] = {a0.x, a0.y, a0.z, a0.w, a1.x, a1.y, a1.z, a1.w};
            float br[8] = {b0.x, b0.y, b0.z, b0.w, b1.x, b1.y, b1.z, b1.w};
#pragma unroll
            for (int i = 0; i < 8; i++)
#pragma unroll
                for (int j = 0; j < 8; j++)
                    acc[i][j] = fmaf(ar[i], br[j], acc[i][j]);
        }
    }

#pragma unroll
    for (int r = 0; r < 8; r++) {
        int oc = oc0 + ty * 8 + r;
        float bb  = pb[oc];
        float inv = gamma[oc] * rsqrtf(var[oc] + 1e-5f);
        float sh  = beta[oc] - mean[oc] * inv;
        float4 v0, v1;
        v0.x = fmaf(acc[r][0] + bb, inv, sh); v0.y = fmaf(acc[r][1] + bb, inv, sh);
        v0.z = fmaf(acc[r][2] + bb, inv, sh); v0.w = fmaf(acc[r][3] + bb, inv, sh);
        v1.x = fmaf(acc[r][4] + bb, inv, sh); v1.y = fmaf(acc[r][5] + bb, inv, sh);
        v1.z = fmaf(acc[r][6] + bb, inv, sh); v1.w = fmaf(acc[r][7] + bb, inv, sh);
        float* o = out + ((size_t)b * DIM_ + oc) * N_ + n0 + tx * 8;
        *(float4*)&o[0] = v0;
        *(float4*)&o[4] = v1;
    }
}

// ======================================================================
extern "C" void kernel_launch(void* const* d_in, const int* in_sizes, int n_in,
                              void* d_out, int out_size) {
    (void)in_sizes; (void)n_in; (void)out_size;
    const float* x      = (const float*)d_in[0];
    const float* qkv_w  = (const float*)d_in[1];
    const float* qkv_b  = (const float*)d_in[2];
    const float* proj_w = (const float*)d_in[3];
    const float* proj_b = (const float*)d_in[4];
    const float* gamma  = (const float*)d_in[5];
    const float* beta   = (const float*)d_in[6];
    const float* mean   = (const float*)d_in[7];
    const float* var    = (const float*)d_in[8];
    float* out = (float*)d_out;

    // opt-in to >48KB dynamic smem (idempotent, not a stream op)
    cudaFuncSetAttribute(k_scores, cudaFuncAttributeMaxDynamicSharedMemorySize,
                         K2_SMEM_BYTES);

    dim3 g1(16, 3, BH_);
    k_qkv<<<g1, 256>>>(x, qkv_w, qkv_b);

    dim3 g2(N_ / 32, BH_);
    k_scores<<<g2, 256, K2_SMEM_BYTES>>>();

    dim3 g3(N_ / 128, BH_);
    k_av<<<g3, 256>>>();

    dim3 g4(N_ / 128, DIM_ / 128, B_);
    k_proj<<<g4, 256>>>(proj_w, proj_b, gamma, beta, mean, var, out);
}